// round 2
// baseline (speedup 1.0000x reference)
#include <cuda_runtime.h>
#include <math.h>

#define B_  8
#define LQ  2048
#define LA  2048
#define HD  1024

#define BM 128
#define BN 128
#define BK 8
#define TM 8
#define TN 8
#define NTHREADS 256

// Scratch (allocation-free): G1 [B, LQ, HD], G [B, LQ, LA], invsum [B, LA]
__device__ float g_G1[(size_t)B_ * LQ * HD];
__device__ float g_G[(size_t)B_ * LQ * LA];
__device__ float g_invsum[B_ * LA];

// ---------------------------------------------------------------------------
// GEMM1: C[M,N] = Q[M,K] @ W[K,N] + bias[N]
//   M = B_*LQ = 16384, N = HD = 1024, K = HD = 1024. All row-major.
// ---------------------------------------------------------------------------
__global__ __launch_bounds__(NTHREADS) void gemm1_kernel(
    const float* __restrict__ Q, const float* __restrict__ W,
    const float* __restrict__ bias, float* __restrict__ C)
{
    const int N = HD, K = HD;
    __shared__ float As[BK][BM];
    __shared__ float Bs[BK][BN];

    const int tid = threadIdx.x;
    const int bm0 = blockIdx.y * BM;
    const int bn0 = blockIdx.x * BN;

    // A (row-major [M,K]) -> transposed into As[k][m]
    const int aRow = tid >> 1;            // 0..127
    const int aCol = (tid & 1) * 4;       // 0 or 4
    // B (row-major [K,N]) -> direct into Bs[k][n]
    const int bRow = tid >> 5;            // 0..7
    const int bCol = (tid & 31) * 4;      // 0..124

    const int tr = (tid >> 4) * TM;
    const int tc = (tid & 15) * TN;

    float acc[TM][TN];
    #pragma unroll
    for (int i = 0; i < TM; ++i)
        #pragma unroll
        for (int j = 0; j < TN; ++j) acc[i][j] = 0.f;

    const float* Aptr = Q + (size_t)(bm0 + aRow) * K + aCol;
    const float* Bptr = W + (size_t)bRow * N + bn0 + bCol;

    for (int k0 = 0; k0 < K; k0 += BK) {
        float4 av = *(const float4*)(Aptr + k0);
        float4 bv = *(const float4*)(Bptr + (size_t)k0 * N);
        As[aCol + 0][aRow] = av.x;
        As[aCol + 1][aRow] = av.y;
        As[aCol + 2][aRow] = av.z;
        As[aCol + 3][aRow] = av.w;
        *(float4*)&Bs[bRow][bCol] = bv;
        __syncthreads();
        #pragma unroll
        for (int k = 0; k < BK; ++k) {
            float4 a0 = *(const float4*)&As[k][tr];
            float4 a1 = *(const float4*)&As[k][tr + 4];
            float4 b0 = *(const float4*)&Bs[k][tc];
            float4 b1 = *(const float4*)&Bs[k][tc + 4];
            float am[8] = {a0.x, a0.y, a0.z, a0.w, a1.x, a1.y, a1.z, a1.w};
            float bn[8] = {b0.x, b0.y, b0.z, b0.w, b1.x, b1.y, b1.z, b1.w};
            #pragma unroll
            for (int i = 0; i < TM; ++i)
                #pragma unroll
                for (int j = 0; j < TN; ++j)
                    acc[i][j] += am[i] * bn[j];
        }
        __syncthreads();
    }

    #pragma unroll
    for (int i = 0; i < TM; ++i) {
        float* crow = C + (size_t)(bm0 + tr + i) * N + bn0 + tc;
        #pragma unroll
        for (int j = 0; j < TN; j += 4) {
            float4 v;
            v.x = acc[i][j + 0] + bias[bn0 + tc + j + 0];
            v.y = acc[i][j + 1] + bias[bn0 + tc + j + 1];
            v.z = acc[i][j + 2] + bias[bn0 + tc + j + 2];
            v.w = acc[i][j + 3] + bias[bn0 + tc + j + 3];
            *(float4*)(crow + j) = v;
        }
    }
}

// ---------------------------------------------------------------------------
// GEMM2 (NT, batched): G[b][M,N] = G1[b][M,K] @ A[b][N,K]^T
//   M = LQ, N = LA, K = HD. Both operands K-contiguous.
// ---------------------------------------------------------------------------
__global__ __launch_bounds__(NTHREADS) void gemm2_kernel(
    const float* __restrict__ G1, const float* __restrict__ Amat,
    float* __restrict__ G)
{
    const int K = HD;
    __shared__ float As[BK][BM];
    __shared__ float Bs[BK][BN];

    const int tid = threadIdx.x;
    const int b = blockIdx.z;
    const int bm0 = blockIdx.y * BM;
    const int bn0 = blockIdx.x * BN;

    const float* Ap = G1   + (size_t)b * LQ * HD;
    const float* Bp = Amat + (size_t)b * LA * HD;
    float*       Cp = G    + (size_t)b * LQ * LA;

    const int ldRow = tid >> 1;           // 0..127 (row within tile)
    const int ldCol = (tid & 1) * 4;      // k offset 0 or 4

    const int tr = (tid >> 4) * TM;
    const int tc = (tid & 15) * TN;

    float acc[TM][TN];
    #pragma unroll
    for (int i = 0; i < TM; ++i)
        #pragma unroll
        for (int j = 0; j < TN; ++j) acc[i][j] = 0.f;

    const float* Aptr = Ap + (size_t)(bm0 + ldRow) * K + ldCol;
    const float* Bptr = Bp + (size_t)(bn0 + ldRow) * K + ldCol;

    for (int k0 = 0; k0 < K; k0 += BK) {
        float4 av = *(const float4*)(Aptr + k0);
        float4 bv = *(const float4*)(Bptr + k0);
        As[ldCol + 0][ldRow] = av.x;
        As[ldCol + 1][ldRow] = av.y;
        As[ldCol + 2][ldRow] = av.z;
        As[ldCol + 3][ldRow] = av.w;
        Bs[ldCol + 0][ldRow] = bv.x;
        Bs[ldCol + 1][ldRow] = bv.y;
        Bs[ldCol + 2][ldRow] = bv.z;
        Bs[ldCol + 3][ldRow] = bv.w;
        __syncthreads();
        #pragma unroll
        for (int k = 0; k < BK; ++k) {
            float4 a0 = *(const float4*)&As[k][tr];
            float4 a1 = *(const float4*)&As[k][tr + 4];
            float4 b0 = *(const float4*)&Bs[k][tc];
            float4 b1 = *(const float4*)&Bs[k][tc + 4];
            float am[8] = {a0.x, a0.y, a0.z, a0.w, a1.x, a1.y, a1.z, a1.w};
            float bn[8] = {b0.x, b0.y, b0.z, b0.w, b1.x, b1.y, b1.z, b1.w};
            #pragma unroll
            for (int i = 0; i < TM; ++i)
                #pragma unroll
                for (int j = 0; j < TN; ++j)
                    acc[i][j] += am[i] * bn[j];
        }
        __syncthreads();
    }

    #pragma unroll
    for (int i = 0; i < TM; ++i) {
        float* crow = Cp + (size_t)(bm0 + tr + i) * LA + bn0 + tc;
        #pragma unroll
        for (int j = 0; j < TN; j += 4) {
            float4 v = {acc[i][j], acc[i][j + 1], acc[i][j + 2], acc[i][j + 3]};
            *(float4*)(crow + j) = v;
        }
    }
}

// ---------------------------------------------------------------------------
// Softmax over q (dim 1): per column (b, a): m = max_q, write exp(x-m),
// store 1/sum. Normalization is folded into GEMM3's epilogue.
// ---------------------------------------------------------------------------
__global__ __launch_bounds__(256) void softmax_kernel(float* __restrict__ G)
{
    const int b = blockIdx.y;
    const int a = blockIdx.x * blockDim.x + threadIdx.x;
    float* base = G + (size_t)b * LQ * LA + a;

    float m = -INFINITY;
    #pragma unroll 4
    for (int q = 0; q < LQ; ++q)
        m = fmaxf(m, base[(size_t)q * LA]);

    float s = 0.f;
    #pragma unroll 4
    for (int q = 0; q < LQ; ++q) {
        float e = expf(base[(size_t)q * LA] - m);
        base[(size_t)q * LA] = e;
        s += e;
    }
    g_invsum[b * LA + a] = 1.0f / s;
}

// ---------------------------------------------------------------------------
// GEMM3 (TN, batched): out[b][M,N] = (G[b]^T)[M,K] @ Q[b][K,N], scaled by
// invsum per output row.
//   M = LA (a), N = HD (h), K = LQ (q).
//   G[b] is stored [K, M] (M contiguous); Q[b] is [K, N] (N contiguous).
// ---------------------------------------------------------------------------
__global__ __launch_bounds__(NTHREADS) void gemm3_kernel(
    const float* __restrict__ G, const float* __restrict__ Q,
    float* __restrict__ Out)
{
    __shared__ float As[BK][BM];
    __shared__ float Bs[BK][BN];

    const int tid = threadIdx.x;
    const int b = blockIdx.z;
    const int bm0 = blockIdx.y * BM;   // a
    const int bn0 = blockIdx.x * BN;   // h

    const float* Ap = G   + (size_t)b * LQ * LA;   // [K=LQ, M=LA]
    const float* Bp = Q   + (size_t)b * LQ * HD;   // [K=LQ, N=HD]
    float*       Cp = Out + (size_t)b * LA * HD;

    const int kRow = tid >> 5;            // 0..7 (k within tile)
    const int mCol = (tid & 31) * 4;      // 0..124

    const int tr = (tid >> 4) * TM;
    const int tc = (tid & 15) * TN;

    float acc[TM][TN];
    #pragma unroll
    for (int i = 0; i < TM; ++i)
        #pragma unroll
        for (int j = 0; j < TN; ++j) acc[i][j] = 0.f;

    const float* Aptr = Ap + (size_t)kRow * LA + bm0 + mCol;
    const float* Bptr = Bp + (size_t)kRow * HD + bn0 + mCol;

    for (int k0 = 0; k0 < LQ; k0 += BK) {
        float4 av = *(const float4*)(Aptr + (size_t)k0 * LA);
        float4 bv = *(const float4*)(Bptr + (size_t)k0 * HD);
        *(float4*)&As[kRow][mCol] = av;
        *(float4*)&Bs[kRow][mCol] = bv;
        __syncthreads();
        #pragma unroll
        for (int k = 0; k < BK; ++k) {
            float4 a0 = *(const float4*)&As[k][tr];
            float4 a1 = *(const float4*)&As[k][tr + 4];
            float4 b0 = *(const float4*)&Bs[k][tc];
            float4 b1 = *(const float4*)&Bs[k][tc + 4];
            float am[8] = {a0.x, a0.y, a0.z, a0.w, a1.x, a1.y, a1.z, a1.w};
            float bn[8] = {b0.x, b0.y, b0.z, b0.w, b1.x, b1.y, b1.z, b1.w};
            #pragma unroll
            for (int i = 0; i < TM; ++i)
                #pragma unroll
                for (int j = 0; j < TN; ++j)
                    acc[i][j] += am[i] * bn[j];
        }
        __syncthreads();
    }

    #pragma unroll
    for (int i = 0; i < TM; ++i) {
        const float inv = g_invsum[b * LA + bm0 + tr + i];
        float* crow = Cp + (size_t)(bm0 + tr + i) * HD + bn0 + tc;
        #pragma unroll
        for (int j = 0; j < TN; j += 4) {
            float4 v = {acc[i][j] * inv, acc[i][j + 1] * inv,
                        acc[i][j + 2] * inv, acc[i][j + 3] * inv};
            *(float4*)(crow + j) = v;
        }
    }
}

// ---------------------------------------------------------------------------
extern "C" void kernel_launch(void* const* d_in, const int* in_sizes, int n_in,
                              void* d_out, int out_size)
{
    const float* q    = (const float*)d_in[0];   // [B, LQ, HD]
    const float* a    = (const float*)d_in[1];   // [B, LA, HD]
    const float* w    = (const float*)d_in[2];   // [HD, HD]
    const float* bias = (const float*)d_in[3];   // [HD]
    float* out = (float*)d_out;                  // [B, LA, HD]

    (void)in_sizes; (void)n_in; (void)out_size;

    // Resolve scratch symbol addresses (host-side API, no allocation).
    float *dG1 = nullptr, *dG = nullptr;
    cudaGetSymbolAddress((void**)&dG1, g_G1);
    cudaGetSymbolAddress((void**)&dG,  g_G);

    // 1) G1 = q @ w + b
    {
        dim3 grid(HD / BN, (B_ * LQ) / BM);
        gemm1_kernel<<<grid, NTHREADS>>>(q, w, bias, dG1);
    }
    // 2) G = G1 @ a^T (batched)
    {
        dim3 grid(LA / BN, LQ / BM, B_);
        gemm2_kernel<<<grid, NTHREADS>>>(dG1, a, dG);
    }
    // 3) column softmax over q: write exp(x - max), stash 1/sum
    {
        dim3 grid(LA / 256, B_);
        softmax_kernel<<<grid, 256>>>(dG);
    }
    // 4) out = G^T @ q, scaled by invsum (batched)
    {
        dim3 grid(HD / BN, LA / BM, B_);
        gemm3_kernel<<<grid, NTHREADS>>>(dG, q, out);
    }
}

// round 6
// speedup vs baseline: 3.1209x; 3.1209x over previous
#include <cuda_runtime.h>
#include <cuda_fp16.h>
#include <math.h>
#include <stdint.h>

#define B_  8
#define LQ  2048
#define LA  2048
#define HD  1024

typedef __half h16;

// ---------------------------------------------------------------------------
// Scratch (static device arrays; allocation-free)
// ---------------------------------------------------------------------------
__device__ __align__(256) h16  g_wT_hi[HD * HD];
__device__ __align__(256) h16  g_wT_lo[HD * HD];
__device__ __align__(256) h16  g_q_hi[(size_t)B_ * LQ * HD];
__device__ __align__(256) h16  g_q_lo[(size_t)B_ * LQ * HD];
__device__ __align__(256) h16  g_qT_hi[(size_t)B_ * HD * LQ];
__device__ __align__(256) h16  g_qT_lo[(size_t)B_ * HD * LQ];
__device__ __align__(256) h16  g_a_hi[(size_t)B_ * LA * HD];
__device__ __align__(256) h16  g_a_lo[(size_t)B_ * LA * HD];
__device__ __align__(256) h16  g_G1_hi[(size_t)B_ * LQ * HD];
__device__ __align__(256) h16  g_G1_lo[(size_t)B_ * LQ * HD];
__device__ __align__(256) float g_G[(size_t)B_ * LA * LQ];      // logits^T [a,q]
__device__ __align__(256) h16  g_P_hi[(size_t)B_ * LA * LQ];
__device__ __align__(256) h16  g_P_lo[(size_t)B_ * LA * LQ];

// ---------------------------------------------------------------------------
// helpers
// ---------------------------------------------------------------------------
__device__ __forceinline__ uint32_t smem_u32(const void* p) {
    uint32_t a;
    asm("{ .reg .u64 t; cvta.to.shared.u64 t, %1; cvt.u32.u64 %0, t; }" : "=r"(a) : "l"(p));
    return a;
}
__device__ __forceinline__ void cp16(uint32_t dst, const void* src) {
    asm volatile("cp.async.cg.shared.global [%0], [%1], 16;" :: "r"(dst), "l"(src) : "memory");
}
#define CP_COMMIT() asm volatile("cp.async.commit_group;" ::: "memory")

__device__ __forceinline__ void ldsm_x4(uint32_t* r, uint32_t addr) {
    asm volatile("ldmatrix.sync.aligned.m8n8.x4.shared.b16 {%0,%1,%2,%3}, [%4];"
                 : "=r"(r[0]), "=r"(r[1]), "=r"(r[2]), "=r"(r[3]) : "r"(addr));
}
__device__ __forceinline__ void ldsm_x2(uint32_t* r, uint32_t addr) {
    asm volatile("ldmatrix.sync.aligned.m8n8.x2.shared.b16 {%0,%1}, [%2];"
                 : "=r"(r[0]), "=r"(r[1]) : "r"(addr));
}
__device__ __forceinline__ void mma16816(float* c, const uint32_t* a, const uint32_t* b) {
    asm volatile(
        "mma.sync.aligned.m16n8k16.row.col.f32.f16.f16.f32 "
        "{%0,%1,%2,%3}, {%4,%5,%6,%7}, {%8,%9}, {%0,%1,%2,%3};"
        : "+f"(c[0]), "+f"(c[1]), "+f"(c[2]), "+f"(c[3])
        : "r"(a[0]), "r"(a[1]), "r"(a[2]), "r"(a[3]), "r"(b[0]), "r"(b[1]));
}

__device__ __forceinline__ void split2(float v, h16& h, h16& l) {
    h = __float2half_rn(v);
    l = __float2half_rn(v - __half2float(h));
}

// ---------------------------------------------------------------------------
// HMMA GEMM (NT): C[M,N] = sum_k (Ahi+Alo)[m,k]*(Bhi+Blo)[n,k]  (lo*lo dropped)
// CTA 128x128, BK=32, 8 warps (2x4) of 64x32, 3-stage cp.async pipeline.
// EPI==0: C = acc + bias[n], split-stored fp16 hi/lo. EPI==1: fp32 store.
// ---------------------------------------------------------------------------
#define TILE_B  8192            // 128 rows x 32 halves x 2B
#define STAGE_B 32768           // 4 tiles (Ah, Al, Bh, Bl)

template<int EPI>
__global__ __launch_bounds__(256) void mm_kernel(
    const h16* __restrict__ Ahi, const h16* __restrict__ Alo,
    const h16* __restrict__ Bhi, const h16* __restrict__ Blo,
    int K, long long sA, long long sB,
    const float* __restrict__ bias,
    float* __restrict__ Cf, long long sC, int ldc,
    h16* __restrict__ Chi, h16* __restrict__ Clo)
{
    extern __shared__ char dsm[];
    const int tid = threadIdx.x;
    const int wid = tid >> 5;
    const int lane = tid & 31;
    const int warp_m = wid >> 2;          // 0..1 (64 rows each)
    const int warp_n = wid & 3;           // 0..3 (32 cols each)
    const int z = blockIdx.z;
    const int bm0 = blockIdx.y * 128;
    const int bn0 = blockIdx.x * 128;

    const uint32_t sbase = (smem_u32(dsm) + 1023u) & ~1023u;

    const h16* pt[4] = {
        Ahi + (size_t)z * sA + (size_t)bm0 * K,
        Alo + (size_t)z * sA + (size_t)bm0 * K,
        Bhi + (size_t)z * sB + (size_t)bn0 * K,
        Blo + (size_t)z * sB + (size_t)bn0 * K };

    // fill one stage: 4 tiles of 128 rows x 32 halves (64B), chunk-XOR swizzle
    auto fill = [&](int stage, int k0) {
        uint32_t sb = sbase + stage * STAGE_B;
        #pragma unroll
        for (int t = 0; t < 4; ++t) {
            #pragma unroll
            for (int rpt = 0; rpt < 2; ++rpt) {
                int idx = rpt * 256 + tid;
                int row = idx >> 2, c = idx & 3;
                uint32_t phys = (uint32_t)(c ^ ((row >> 1) & 3));
                uint32_t dst = sb + t * TILE_B + row * 64 + phys * 16;
                cp16(dst, pt[t] + (size_t)row * K + k0 + c * 8);
            }
        }
        CP_COMMIT();
    };

    float acc[4][4][4];
    #pragma unroll
    for (int i = 0; i < 4; ++i)
        #pragma unroll
        for (int j = 0; j < 4; ++j)
            #pragma unroll
            for (int k = 0; k < 4; ++k) acc[i][j][k] = 0.f;

    const int NK = K >> 5;
    fill(0, 0);
    fill(1, 32);

    for (int i = 0; i < NK; ++i) {
        if (i + 1 < NK) asm volatile("cp.async.wait_group 1;" ::: "memory");
        else            asm volatile("cp.async.wait_group 0;" ::: "memory");
        __syncthreads();
        if (i + 2 < NK) fill((i + 2) % 3, (i + 2) * 32);

        const uint32_t sb  = sbase + (i % 3) * STAGE_B;
        const uint32_t bAh = sb;
        const uint32_t bAl = sb + TILE_B;
        const uint32_t bBh = sb + 2 * TILE_B;
        const uint32_t bBl = sb + 3 * TILE_B;

        #pragma unroll
        for (int ks = 0; ks < 2; ++ks) {
            uint32_t aH[4][4], aL[4][4], bH[4][2], bL[4][2];
            // A addresses: 16 rows x (2 chunk-halves), chunk = ks*2 + lane/16
            #pragma unroll
            for (int mt = 0; mt < 4; ++mt) {
                int row = warp_m * 64 + mt * 16 + (lane & 15);
                int c = ks * 2 + (lane >> 4);
                uint32_t addr = bAh + row * 64 + (uint32_t)(c ^ ((row >> 1) & 3)) * 16;
                ldsm_x4(aH[mt], addr);
            }
            #pragma unroll
            for (int nt = 0; nt < 4; ++nt) {
                int row = warp_n * 32 + nt * 8 + (lane & 7);
                int c = ks * 2 + ((lane >> 3) & 1);
                uint32_t addr = bBh + row * 64 + (uint32_t)(c ^ ((row >> 1) & 3)) * 16;
                ldsm_x2(bH[nt], addr);
            }
            #pragma unroll
            for (int mt = 0; mt < 4; ++mt)
                #pragma unroll
                for (int nt = 0; nt < 4; ++nt) mma16816(acc[mt][nt], aH[mt], bH[nt]);

            #pragma unroll
            for (int nt = 0; nt < 4; ++nt) {
                int row = warp_n * 32 + nt * 8 + (lane & 7);
                int c = ks * 2 + ((lane >> 3) & 1);
                uint32_t addr = bBl + row * 64 + (uint32_t)(c ^ ((row >> 1) & 3)) * 16;
                ldsm_x2(bL[nt], addr);
            }
            #pragma unroll
            for (int mt = 0; mt < 4; ++mt)
                #pragma unroll
                for (int nt = 0; nt < 4; ++nt) mma16816(acc[mt][nt], aH[mt], bL[nt]);

            #pragma unroll
            for (int mt = 0; mt < 4; ++mt) {
                int row = warp_m * 64 + mt * 16 + (lane & 15);
                int c = ks * 2 + (lane >> 4);
                uint32_t addr = bAl + row * 64 + (uint32_t)(c ^ ((row >> 1) & 3)) * 16;
                ldsm_x4(aL[mt], addr);
            }
            #pragma unroll
            for (int mt = 0; mt < 4; ++mt)
                #pragma unroll
                for (int nt = 0; nt < 4; ++nt) mma16816(acc[mt][nt], aL[mt], bH[nt]);
        }
        __syncthreads();
    }

    // epilogue
    #pragma unroll
    for (int mt = 0; mt < 4; ++mt) {
        #pragma unroll
        for (int nt = 0; nt < 4; ++nt) {
            const int m0 = bm0 + warp_m * 64 + mt * 16 + (lane >> 2);
            const int n0 = bn0 + warp_n * 32 + nt * 8 + 2 * (lane & 3);
            float* c = acc[mt][nt];
            if (EPI == 1) {
                float* r0 = Cf + (size_t)z * sC + (size_t)m0 * ldc + n0;
                float* r1 = Cf + (size_t)z * sC + (size_t)(m0 + 8) * ldc + n0;
                *(float2*)r0 = make_float2(c[0], c[1]);
                *(float2*)r1 = make_float2(c[2], c[3]);
            } else {
                float b0 = bias[n0], b1 = bias[n0 + 1];
                h16 h0, l0, h1, l1;
                split2(c[0] + b0, h0, l0); split2(c[1] + b1, h1, l1);
                *(__half2*)(Chi + (size_t)m0 * ldc + n0) = __halves2half2(h0, h1);
                *(__half2*)(Clo + (size_t)m0 * ldc + n0) = __halves2half2(l0, l1);
                split2(c[2] + b0, h0, l0); split2(c[3] + b1, h1, l1);
                *(__half2*)(Chi + (size_t)(m0 + 8) * ldc + n0) = __halves2half2(h0, h1);
                *(__half2*)(Clo + (size_t)(m0 + 8) * ldc + n0) = __halves2half2(l0, l1);
            }
        }
    }
}

// ---------------------------------------------------------------------------
// elementwise fp32 -> (hi, lo) fp16 split
// ---------------------------------------------------------------------------
__global__ __launch_bounds__(256) void split_kernel(
    const float4* __restrict__ in, __half2* __restrict__ hi,
    __half2* __restrict__ lo, int n4)
{
    int i = blockIdx.x * 256 + threadIdx.x;
    if (i >= n4) return;
    float4 v = in[i];
    h16 h0, l0, h1, l1, h2, l2, h3, l3;
    split2(v.x, h0, l0); split2(v.y, h1, l1);
    split2(v.z, h2, l2); split2(v.w, h3, l3);
    hi[2 * i + 0] = __halves2half2(h0, h1);
    hi[2 * i + 1] = __halves2half2(h2, h3);
    lo[2 * i + 0] = __halves2half2(l0, l1);
    lo[2 * i + 1] = __halves2half2(l2, l3);
}

// ---------------------------------------------------------------------------
// batched transpose + split: in [R, C] fp32 -> out [C, R] (hi, lo) fp16
// ---------------------------------------------------------------------------
__global__ __launch_bounds__(256) void transpose_split_kernel(
    const float* __restrict__ in, h16* __restrict__ ohi, h16* __restrict__ olo,
    int R, int C)
{
    __shared__ float t[32][33];
    const size_t bofs = (size_t)blockIdx.z * R * C;
    const float* ip = in + bofs;
    const int c0 = blockIdx.x * 32, r0 = blockIdx.y * 32;
    const int x = threadIdx.x & 31;
    const int ty = threadIdx.x >> 5;   // 0..7
    #pragma unroll
    for (int dy = 0; dy < 32; dy += 8)
        t[ty + dy][x] = ip[(size_t)(r0 + ty + dy) * C + c0 + x];
    __syncthreads();
    #pragma unroll
    for (int dy = 0; dy < 32; dy += 8) {
        float v = t[x][ty + dy];
        h16 h, l; split2(v, h, l);
        size_t oidx = bofs + (size_t)(c0 + ty + dy) * R + r0 + x;
        ohi[oidx] = h;
        olo[oidx] = l;
    }
}

// ---------------------------------------------------------------------------
// row softmax over q (rows of G^T [B*LA, LQ]); writes split probs * 1/sum
// ---------------------------------------------------------------------------
__global__ __launch_bounds__(256) void softmax_split_kernel(
    const float* __restrict__ G, h16* __restrict__ Phi, h16* __restrict__ Plo)
{
    __shared__ float buf[LQ];
    __shared__ float red[256];
    const size_t row = blockIdx.x;
    const float* g = G + row * LQ;
    const int tid = threadIdx.x;

    float m = -INFINITY;
    #pragma unroll
    for (int i = tid; i < LQ; i += 256) { float v = g[i]; buf[i] = v; m = fmaxf(m, v); }
    red[tid] = m; __syncthreads();
    #pragma unroll
    for (int s = 128; s > 0; s >>= 1) {
        if (tid < s) red[tid] = fmaxf(red[tid], red[tid + s]);
        __syncthreads();
    }
    m = red[0]; __syncthreads();

    float ssum = 0.f;
    #pragma unroll
    for (int i = tid; i < LQ; i += 256) { float e = __expf(buf[i] - m); buf[i] = e; ssum += e; }
    red[tid] = ssum; __syncthreads();
    #pragma unroll
    for (int s = 128; s > 0; s >>= 1) {
        if (tid < s) red[tid] += red[tid + s];
        __syncthreads();
    }
    const float inv = 1.0f / red[0];

    #pragma unroll
    for (int i = tid; i < LQ; i += 256) {
        float p = buf[i] * inv;
        h16 h, l; split2(p, h, l);
        Phi[row * LQ + i] = h;
        Plo[row * LQ + i] = l;
    }
}

// ---------------------------------------------------------------------------
extern "C" void kernel_launch(void* const* d_in, const int* in_sizes, int n_in,
                              void* d_out, int out_size)
{
    const float* q    = (const float*)d_in[0];   // [B, LQ, HD]
    const float* a    = (const float*)d_in[1];   // [B, LA, HD]
    const float* w    = (const float*)d_in[2];   // [HD, HD]
    const float* bias = (const float*)d_in[3];   // [HD]
    float* out = (float*)d_out;                  // [B, LA, HD]
    (void)in_sizes; (void)n_in; (void)out_size;

    h16 *wTh, *wTl, *qh, *ql, *qTh, *qTl, *ah, *al, *g1h, *g1l, *ph, *pl;
    float* G;
    cudaGetSymbolAddress((void**)&wTh, g_wT_hi);
    cudaGetSymbolAddress((void**)&wTl, g_wT_lo);
    cudaGetSymbolAddress((void**)&qh,  g_q_hi);
    cudaGetSymbolAddress((void**)&ql,  g_q_lo);
    cudaGetSymbolAddress((void**)&qTh, g_qT_hi);
    cudaGetSymbolAddress((void**)&qTl, g_qT_lo);
    cudaGetSymbolAddress((void**)&ah,  g_a_hi);
    cudaGetSymbolAddress((void**)&al,  g_a_lo);
    cudaGetSymbolAddress((void**)&g1h, g_G1_hi);
    cudaGetSymbolAddress((void**)&g1l, g_G1_lo);
    cudaGetSymbolAddress((void**)&G,   g_G);
    cudaGetSymbolAddress((void**)&ph,  g_P_hi);
    cudaGetSymbolAddress((void**)&pl,  g_P_lo);

    const int dyn_smem = 3 * STAGE_B + 1024;
    cudaFuncSetAttribute(mm_kernel<0>, cudaFuncAttributeMaxDynamicSharedMemorySize, dyn_smem);
    cudaFuncSetAttribute(mm_kernel<1>, cudaFuncAttributeMaxDynamicSharedMemorySize, dyn_smem);

    // 1) input conversions
    {
        int n4 = (B_ * LQ * HD) / 4;
        split_kernel<<<n4 / 256, 256>>>((const float4*)q, (__half2*)qh, (__half2*)ql, n4);
        split_kernel<<<n4 / 256, 256>>>((const float4*)a, (__half2*)ah, (__half2*)al, n4);
    }
    {
        dim3 grid(HD / 32, HD / 32, 1);
        transpose_split_kernel<<<grid, 256>>>(w, wTh, wTl, HD, HD);     // wT [n][k]
    }
    {
        dim3 grid(HD / 32, LQ / 32, B_);
        transpose_split_kernel<<<grid, 256>>>(q, qTh, qTl, LQ, HD);     // qT [h][q]
    }

    // 2) G1 = q @ w + b  (M=B*LQ, N=HD, K=HD), split-stored fp16
    {
        dim3 grid(HD / 128, (B_ * LQ) / 128, 1);
        mm_kernel<0><<<grid, 256, dyn_smem>>>(qh, ql, wTh, wTl, HD, 0, 0,
                                              bias, nullptr, 0, HD, g1h, g1l);
    }
    // 3) G^T[a,q] = a @ G1^T  (per batch M=LA, N=LQ, K=HD), fp32
    {
        dim3 grid(LQ / 128, LA / 128, B_);
        mm_kernel<1><<<grid, 256, dyn_smem>>>(ah, al, g1h, g1l, HD,
                                              (long long)LA * HD, (long long)LQ * HD,
                                              nullptr, G, (long long)LA * LQ, LQ,
                                              nullptr, nullptr);
    }
    // 4) row softmax over q + split probs
    softmax_split_kernel<<<B_ * LA, 256>>>(G, ph, pl);

    // 5) out[a,h] = P[a,q] @ qT[h,q]^T  (per batch M=LA, N=HD, K=LQ), fp32
    {
        dim3 grid(HD / 128, LA / 128, B_);
        mm_kernel<1><<<grid, 256, dyn_smem>>>(ph, pl, qTh, qTl, LQ,
                                              (long long)LA * LQ, (long long)HD * LQ,
                                              nullptr, out, (long long)LA * HD, HD,
                                              nullptr, nullptr);
    }
}

// round 7
// speedup vs baseline: 3.9336x; 1.2604x over previous
#include <cuda_runtime.h>
#include <cuda_fp16.h>
#include <math.h>
#include <stdint.h>

#define B_  8
#define LQ  2048
#define LA  2048
#define HD  1024

typedef __half h16;

// ---------------------------------------------------------------------------
// Scratch (static device arrays; allocation-free)
// ---------------------------------------------------------------------------
__device__ __align__(256) h16  g_wT_hi[HD * HD];
__device__ __align__(256) h16  g_wT_lo[HD * HD];
__device__ __align__(256) h16  g_q_hi[(size_t)B_ * LQ * HD];
__device__ __align__(256) h16  g_q_lo[(size_t)B_ * LQ * HD];
__device__ __align__(256) h16  g_qT_hi[(size_t)B_ * HD * LQ];
__device__ __align__(256) h16  g_qT_lo[(size_t)B_ * HD * LQ];
__device__ __align__(256) h16  g_a_hi[(size_t)B_ * LA * HD];
__device__ __align__(256) h16  g_a_lo[(size_t)B_ * LA * HD];
__device__ __align__(256) h16  g_G1_hi[(size_t)B_ * LQ * HD];
__device__ __align__(256) h16  g_G1_lo[(size_t)B_ * LQ * HD];
__device__ __align__(256) float g_G[(size_t)B_ * LA * LQ];      // logits^T [a,q]
__device__ __align__(256) h16  g_P_hi[(size_t)B_ * LA * LQ];
__device__ __align__(256) h16  g_P_lo[(size_t)B_ * LA * LQ];

// ---------------------------------------------------------------------------
// helpers
// ---------------------------------------------------------------------------
__device__ __forceinline__ uint32_t smem_u32(const void* p) {
    uint32_t a;
    asm("{ .reg .u64 t; cvta.to.shared.u64 t, %1; cvt.u32.u64 %0, t; }" : "=r"(a) : "l"(p));
    return a;
}
__device__ __forceinline__ void cp16(uint32_t dst, const void* src) {
    asm volatile("cp.async.cg.shared.global [%0], [%1], 16;" :: "r"(dst), "l"(src) : "memory");
}
#define CP_COMMIT() asm volatile("cp.async.commit_group;" ::: "memory")

__device__ __forceinline__ void ldsm_x4(uint32_t* r, uint32_t addr) {
    asm volatile("ldmatrix.sync.aligned.m8n8.x4.shared.b16 {%0,%1,%2,%3}, [%4];"
                 : "=r"(r[0]), "=r"(r[1]), "=r"(r[2]), "=r"(r[3]) : "r"(addr));
}
__device__ __forceinline__ void mma16816(float* c, const uint32_t* a, const uint32_t* b) {
    asm volatile(
        "mma.sync.aligned.m16n8k16.row.col.f32.f16.f16.f32 "
        "{%0,%1,%2,%3}, {%4,%5,%6,%7}, {%8,%9}, {%0,%1,%2,%3};"
        : "+f"(c[0]), "+f"(c[1]), "+f"(c[2]), "+f"(c[3])
        : "r"(a[0]), "r"(a[1]), "r"(a[2]), "r"(a[3]), "r"(b[0]), "r"(b[1]));
}

__device__ __forceinline__ void split2(float v, h16& h, h16& l) {
    h = __float2half_rn(v);
    l = __float2half_rn(v - __half2float(h));
}

// ---------------------------------------------------------------------------
// HMMA GEMM (NT): C[M,N] = sum_k (Ahi+Alo)[m,k]*(Bhi+Blo)[n,k]
// TERMS==3: AhBh + AhBl + AlBh.  TERMS==2: AhBh + AlBh (B-lo dropped).
// CTA 128x128, BK=32, 8 warps (2x4) of 64x32, 3-stage cp.async pipeline.
// EPI==0: C = acc + bias[n], split-stored fp16 hi/lo. EPI==1: fp32 store.
// ---------------------------------------------------------------------------
#define TILE_B  8192            // 128 rows x 32 halves x 2B
#define STAGE_B 32768           // 4 tiles (Ah, Al, Bh, Bl)

template<int EPI, int TERMS>
__global__ __launch_bounds__(256) void mm_kernel(
    const h16* __restrict__ Ahi, const h16* __restrict__ Alo,
    const h16* __restrict__ Bhi, const h16* __restrict__ Blo,
    int K, long long sA, long long sB,
    const float* __restrict__ bias,
    float* __restrict__ Cf, long long sC, int ldc,
    h16* __restrict__ Chi, h16* __restrict__ Clo)
{
    extern __shared__ char dsm[];
    const int tid = threadIdx.x;
    const int wid = tid >> 5;
    const int lane = tid & 31;
    const int warp_m = wid >> 2;          // 0..1 (64 rows each)
    const int warp_n = wid & 3;           // 0..3 (32 cols each)
    const int z = blockIdx.z;
    const int bm0 = blockIdx.y * 128;
    const int bn0 = blockIdx.x * 128;

    const uint32_t sbase = (smem_u32(dsm) + 1023u) & ~1023u;

    const h16* pt[4] = {
        Ahi + (size_t)z * sA + (size_t)bm0 * K,
        Alo + (size_t)z * sA + (size_t)bm0 * K,
        Bhi + (size_t)z * sB + (size_t)bn0 * K,
        Blo + (size_t)z * sB + (size_t)bn0 * K };

    // fill one stage: tiles of 128 rows x 32 halves (64B), chunk-XOR swizzle
    auto fill = [&](int stage, int k0) {
        uint32_t sb = sbase + stage * STAGE_B;
        #pragma unroll
        for (int t = 0; t < 4; ++t) {
            if (TERMS == 2 && t == 3) continue;   // B-lo tile unused
            #pragma unroll
            for (int rpt = 0; rpt < 2; ++rpt) {
                int idx = rpt * 256 + tid;
                int row = idx >> 2, c = idx & 3;
                uint32_t phys = (uint32_t)(c ^ ((row >> 1) & 3));
                uint32_t dst = sb + t * TILE_B + row * 64 + phys * 16;
                cp16(dst, pt[t] + (size_t)row * K + k0 + c * 8);
            }
        }
        CP_COMMIT();
    };

    float acc[4][4][4];
    #pragma unroll
    for (int i = 0; i < 4; ++i)
        #pragma unroll
        for (int j = 0; j < 4; ++j)
            #pragma unroll
            for (int k = 0; k < 4; ++k) acc[i][j][k] = 0.f;

    const int NK = K >> 5;
    fill(0, 0);
    fill(1, 32);

    for (int i = 0; i < NK; ++i) {
        if (i + 1 < NK) asm volatile("cp.async.wait_group 1;" ::: "memory");
        else            asm volatile("cp.async.wait_group 0;" ::: "memory");
        __syncthreads();
        if (i + 2 < NK) fill((i + 2) % 3, (i + 2) * 32);

        const uint32_t sb  = sbase + (i % 3) * STAGE_B;
        const uint32_t bAh = sb;
        const uint32_t bAl = sb + TILE_B;
        const uint32_t bBh = sb + 2 * TILE_B;
        const uint32_t bBl = sb + 3 * TILE_B;

        // B x4 ldsm address: grp 0..3 -> {nt_even k-lo, nt_even k-hi,
        //                                nt_odd k-lo, nt_odd k-hi}
        const int grp = lane >> 3;
        const int bro = warp_n * 32 + ((grp >> 1) & 1) * 8 + (lane & 7);
        const int gch = grp & 1;

        #pragma unroll
        for (int ks = 0; ks < 2; ++ks) {
            uint32_t aH[4][4], aL[4][4], bH[8], bL[8];
            // A hi: 4 x4 loads (16 rows x 16 k each)
            #pragma unroll
            for (int mt = 0; mt < 4; ++mt) {
                int row = warp_m * 64 + mt * 16 + (lane & 15);
                int c = ks * 2 + (lane >> 4);
                uint32_t addr = bAh + row * 64 + (uint32_t)(c ^ ((row >> 1) & 3)) * 16;
                ldsm_x4(aH[mt], addr);
            }
            // B hi: 2 x4 loads cover nt 0..3, both k halves
            #pragma unroll
            for (int p = 0; p < 2; ++p) {
                int row = bro + p * 16;
                int c = ks * 2 + gch;
                uint32_t addr = bBh + row * 64 + (uint32_t)(c ^ ((row >> 1) & 3)) * 16;
                ldsm_x4(&bH[p * 4], addr);
            }
            #pragma unroll
            for (int mt = 0; mt < 4; ++mt)
                #pragma unroll
                for (int nt = 0; nt < 4; ++nt) mma16816(acc[mt][nt], aH[mt], &bH[nt * 2]);

            if (TERMS == 3) {
                #pragma unroll
                for (int p = 0; p < 2; ++p) {
                    int row = bro + p * 16;
                    int c = ks * 2 + gch;
                    uint32_t addr = bBl + row * 64 + (uint32_t)(c ^ ((row >> 1) & 3)) * 16;
                    ldsm_x4(&bL[p * 4], addr);
                }
                #pragma unroll
                for (int mt = 0; mt < 4; ++mt)
                    #pragma unroll
                    for (int nt = 0; nt < 4; ++nt) mma16816(acc[mt][nt], aH[mt], &bL[nt * 2]);
            }

            // A lo
            #pragma unroll
            for (int mt = 0; mt < 4; ++mt) {
                int row = warp_m * 64 + mt * 16 + (lane & 15);
                int c = ks * 2 + (lane >> 4);
                uint32_t addr = bAl + row * 64 + (uint32_t)(c ^ ((row >> 1) & 3)) * 16;
                ldsm_x4(aL[mt], addr);
            }
            #pragma unroll
            for (int mt = 0; mt < 4; ++mt)
                #pragma unroll
                for (int nt = 0; nt < 4; ++nt) mma16816(acc[mt][nt], aL[mt], &bH[nt * 2]);
        }
        __syncthreads();
    }

    // epilogue
    #pragma unroll
    for (int mt = 0; mt < 4; ++mt) {
        #pragma unroll
        for (int nt = 0; nt < 4; ++nt) {
            const int m0 = bm0 + warp_m * 64 + mt * 16 + (lane >> 2);
            const int n0 = bn0 + warp_n * 32 + nt * 8 + 2 * (lane & 3);
            float* c = acc[mt][nt];
            if (EPI == 1) {
                float* r0 = Cf + (size_t)z * sC + (size_t)m0 * ldc + n0;
                float* r1 = Cf + (size_t)z * sC + (size_t)(m0 + 8) * ldc + n0;
                *(float2*)r0 = make_float2(c[0], c[1]);
                *(float2*)r1 = make_float2(c[2], c[3]);
            } else {
                float b0 = bias[n0], b1 = bias[n0 + 1];
                h16 h0, l0, h1, l1;
                split2(c[0] + b0, h0, l0); split2(c[1] + b1, h1, l1);
                *(__half2*)(Chi + (size_t)m0 * ldc + n0) = __halves2half2(h0, h1);
                *(__half2*)(Clo + (size_t)m0 * ldc + n0) = __halves2half2(l0, l1);
                split2(c[2] + b0, h0, l0); split2(c[3] + b1, h1, l1);
                *(__half2*)(Chi + (size_t)(m0 + 8) * ldc + n0) = __halves2half2(h0, h1);
                *(__half2*)(Clo + (size_t)(m0 + 8) * ldc + n0) = __halves2half2(l0, l1);
            }
        }
    }
}

// ---------------------------------------------------------------------------
// elementwise fp32 -> (hi, lo) fp16 split
// ---------------------------------------------------------------------------
__global__ __launch_bounds__(256) void split_kernel(
    const float4* __restrict__ in, __half2* __restrict__ hi,
    __half2* __restrict__ lo, int n4)
{
    int i = blockIdx.x * 256 + threadIdx.x;
    if (i >= n4) return;
    float4 v = in[i];
    h16 h0, l0, h1, l1, h2, l2, h3, l3;
    split2(v.x, h0, l0); split2(v.y, h1, l1);
    split2(v.z, h2, l2); split2(v.w, h3, l3);
    hi[2 * i + 0] = __halves2half2(h0, h1);
    hi[2 * i + 1] = __halves2half2(h2, h3);
    lo[2 * i + 0] = __halves2half2(l0, l1);
    lo[2 * i + 1] = __halves2half2(l2, l3);
}

// ---------------------------------------------------------------------------
// batched transpose + split: in [R, C] fp32 -> out [C, R] (hi, lo) fp16
// ---------------------------------------------------------------------------
__global__ __launch_bounds__(256) void transpose_split_kernel(
    const float* __restrict__ in, h16* __restrict__ ohi, h16* __restrict__ olo,
    int R, int C)
{
    __shared__ float t[32][33];
    const size_t bofs = (size_t)blockIdx.z * R * C;
    const float* ip = in + bofs;
    const int c0 = blockIdx.x * 32, r0 = blockIdx.y * 32;
    const int x = threadIdx.x & 31;
    const int ty = threadIdx.x >> 5;   // 0..7
    #pragma unroll
    for (int dy = 0; dy < 32; dy += 8)
        t[ty + dy][x] = ip[(size_t)(r0 + ty + dy) * C + c0 + x];
    __syncthreads();
    #pragma unroll
    for (int dy = 0; dy < 32; dy += 8) {
        float v = t[x][ty + dy];
        h16 h, l; split2(v, h, l);
        size_t oidx = bofs + (size_t)(c0 + ty + dy) * R + r0 + x;
        ohi[oidx] = h;
        olo[oidx] = l;
    }
}

// ---------------------------------------------------------------------------
// row softmax over q (rows of G^T [B*LA, LQ]); writes split probs * 1/sum.
// Register-resident row (8 floats/thread), float4 I/O.
// ---------------------------------------------------------------------------
__global__ __launch_bounds__(256) void softmax_split_kernel(
    const float* __restrict__ G, h16* __restrict__ Phi, h16* __restrict__ Plo)
{
    __shared__ float red[256];
    const size_t row = blockIdx.x;
    const float4* g4 = (const float4*)(G + row * LQ);
    const int tid = threadIdx.x;

    float4 v[2];
    v[0] = g4[tid];
    v[1] = g4[tid + 256];

    float m = fmaxf(fmaxf(fmaxf(v[0].x, v[0].y), fmaxf(v[0].z, v[0].w)),
                    fmaxf(fmaxf(v[1].x, v[1].y), fmaxf(v[1].z, v[1].w)));
    red[tid] = m; __syncthreads();
    #pragma unroll
    for (int s = 128; s > 0; s >>= 1) {
        if (tid < s) red[tid] = fmaxf(red[tid], red[tid + s]);
        __syncthreads();
    }
    m = red[0]; __syncthreads();

    float ssum = 0.f;
    #pragma unroll
    for (int k = 0; k < 2; ++k) {
        v[k].x = __expf(v[k].x - m); ssum += v[k].x;
        v[k].y = __expf(v[k].y - m); ssum += v[k].y;
        v[k].z = __expf(v[k].z - m); ssum += v[k].z;
        v[k].w = __expf(v[k].w - m); ssum += v[k].w;
    }
    red[tid] = ssum; __syncthreads();
    #pragma unroll
    for (int s = 128; s > 0; s >>= 1) {
        if (tid < s) red[tid] += red[tid + s];
        __syncthreads();
    }
    const float inv = 1.0f / red[0];

    __half2* ph2 = (__half2*)(Phi + row * LQ);
    __half2* pl2 = (__half2*)(Plo + row * LQ);
    #pragma unroll
    for (int k = 0; k < 2; ++k) {
        int base = (tid + k * 256) * 2;
        h16 h0, l0, h1, l1;
        split2(v[k].x * inv, h0, l0); split2(v[k].y * inv, h1, l1);
        ph2[base] = __halves2half2(h0, h1);
        pl2[base] = __halves2half2(l0, l1);
        split2(v[k].z * inv, h0, l0); split2(v[k].w * inv, h1, l1);
        ph2[base + 1] = __halves2half2(h0, h1);
        pl2[base + 1] = __halves2half2(l0, l1);
    }
}

// ---------------------------------------------------------------------------
extern "C" void kernel_launch(void* const* d_in, const int* in_sizes, int n_in,
                              void* d_out, int out_size)
{
    const float* q    = (const float*)d_in[0];   // [B, LQ, HD]
    const float* a    = (const float*)d_in[1];   // [B, LA, HD]
    const float* w    = (const float*)d_in[2];   // [HD, HD]
    const float* bias = (const float*)d_in[3];   // [HD]
    float* out = (float*)d_out;                  // [B, LA, HD]
    (void)in_sizes; (void)n_in; (void)out_size;

    h16 *wTh, *wTl, *qh, *ql, *qTh, *qTl, *ah, *al, *g1h, *g1l, *ph, *pl;
    float* G;
    cudaGetSymbolAddress((void**)&wTh, g_wT_hi);
    cudaGetSymbolAddress((void**)&wTl, g_wT_lo);
    cudaGetSymbolAddress((void**)&qh,  g_q_hi);
    cudaGetSymbolAddress((void**)&ql,  g_q_lo);
    cudaGetSymbolAddress((void**)&qTh, g_qT_hi);
    cudaGetSymbolAddress((void**)&qTl, g_qT_lo);
    cudaGetSymbolAddress((void**)&ah,  g_a_hi);
    cudaGetSymbolAddress((void**)&al,  g_a_lo);
    cudaGetSymbolAddress((void**)&g1h, g_G1_hi);
    cudaGetSymbolAddress((void**)&g1l, g_G1_lo);
    cudaGetSymbolAddress((void**)&G,   g_G);
    cudaGetSymbolAddress((void**)&ph,  g_P_hi);
    cudaGetSymbolAddress((void**)&pl,  g_P_lo);

    const int dyn_smem = 3 * STAGE_B + 1024;
    cudaFuncSetAttribute(mm_kernel<0,3>, cudaFuncAttributeMaxDynamicSharedMemorySize, dyn_smem);
    cudaFuncSetAttribute(mm_kernel<1,3>, cudaFuncAttributeMaxDynamicSharedMemorySize, dyn_smem);
    cudaFuncSetAttribute(mm_kernel<1,2>, cudaFuncAttributeMaxDynamicSharedMemorySize, dyn_smem);

    // 1) input conversions
    {
        int n4 = (B_ * LQ * HD) / 4;
        split_kernel<<<n4 / 256, 256>>>((const float4*)q, (__half2*)qh, (__half2*)ql, n4);
        split_kernel<<<n4 / 256, 256>>>((const float4*)a, (__half2*)ah, (__half2*)al, n4);
    }
    {
        dim3 grid(HD / 32, HD / 32, 1);
        transpose_split_kernel<<<grid, 256>>>(w, wTh, wTl, HD, HD);     // wT [n][k]
    }
    {
        dim3 grid(HD / 32, LQ / 32, B_);
        transpose_split_kernel<<<grid, 256>>>(q, qTh, qTl, LQ, HD);     // qT [h][q]
    }

    // 2) G1 = q @ w + b  (M=B*LQ, N=HD, K=HD), split-stored fp16
    {
        dim3 grid(HD / 128, (B_ * LQ) / 128, 1);
        mm_kernel<0,3><<<grid, 256, dyn_smem>>>(qh, ql, wTh, wTl, HD, 0, 0,
                                                bias, nullptr, 0, HD, g1h, g1l);
    }
    // 3) G^T[a,q] = a @ G1^T  (per batch M=LA, N=LQ, K=HD), fp32
    {
        dim3 grid(LQ / 128, LA / 128, B_);
        mm_kernel<1,3><<<grid, 256, dyn_smem>>>(ah, al, g1h, g1l, HD,
                                                (long long)LA * HD, (long long)LQ * HD,
                                                nullptr, G, (long long)LA * LQ, LQ,
                                                nullptr, nullptr);
    }
    // 4) row softmax over q + split probs
    softmax_split_kernel<<<B_ * LA, 256>>>(G, ph, pl);

    // 5) out[a,h] = P[a,q] @ qT[h,q]^T  (per batch M=LA, N=HD, K=LQ),
    //    2-term (q_lo dropped), fp32
    {
        dim3 grid(HD / 128, LA / 128, B_);
        mm_kernel<1,2><<<grid, 256, dyn_smem>>>(ph, pl, qTh, qTl, LQ,
                                                (long long)LA * LQ, (long long)HD * LQ,
                                                nullptr, out, (long long)LA * HD, HD,
                                                nullptr, nullptr);
    }
}

// round 8
// speedup vs baseline: 4.0942x; 1.0408x over previous
#include <cuda_runtime.h>
#include <cuda_fp16.h>
#include <math.h>
#include <stdint.h>

#define B_  8
#define LQ  2048
#define LA  2048
#define HD  1024

typedef __half h16;

// ---------------------------------------------------------------------------
// Scratch (static device arrays; allocation-free)
// ---------------------------------------------------------------------------
__device__ __align__(256) h16  g_wT_hi[HD * HD];
__device__ __align__(256) h16  g_wT_lo[HD * HD];
__device__ __align__(256) h16  g_q_hi[(size_t)B_ * LQ * HD];
__device__ __align__(256) h16  g_q_lo[(size_t)B_ * LQ * HD];
__device__ __align__(256) h16  g_qT_hi[(size_t)B_ * HD * LQ];
__device__ __align__(256) h16  g_qT_lo[(size_t)B_ * HD * LQ];
__device__ __align__(256) h16  g_a_hi[(size_t)B_ * LA * HD];
__device__ __align__(256) h16  g_a_lo[(size_t)B_ * LA * HD];
__device__ __align__(256) h16  g_G1_hi[(size_t)B_ * LQ * HD];
__device__ __align__(256) h16  g_G1_lo[(size_t)B_ * LQ * HD];
__device__ __align__(256) float g_G[(size_t)B_ * LA * LQ];      // logits^T [a,q]
__device__ __align__(256) h16  g_P_hi[(size_t)B_ * LA * LQ];
__device__ __align__(256) h16  g_P_lo[(size_t)B_ * LA * LQ];

// ---------------------------------------------------------------------------
// helpers
// ---------------------------------------------------------------------------
__device__ __forceinline__ uint32_t smem_u32(const void* p) {
    uint32_t a;
    asm("{ .reg .u64 t; cvta.to.shared.u64 t, %1; cvt.u32.u64 %0, t; }" : "=r"(a) : "l"(p));
    return a;
}
__device__ __forceinline__ void cp16(uint32_t dst, const void* src) {
    asm volatile("cp.async.cg.shared.global [%0], [%1], 16;" :: "r"(dst), "l"(src) : "memory");
}
#define CP_COMMIT() asm volatile("cp.async.commit_group;" ::: "memory")

__device__ __forceinline__ void ldsm_x4(uint32_t* r, uint32_t addr) {
    asm volatile("ldmatrix.sync.aligned.m8n8.x4.shared.b16 {%0,%1,%2,%3}, [%4];"
                 : "=r"(r[0]), "=r"(r[1]), "=r"(r[2]), "=r"(r[3]) : "r"(addr));
}
__device__ __forceinline__ void mma16816(float* c, const uint32_t* a, const uint32_t* b) {
    asm volatile(
        "mma.sync.aligned.m16n8k16.row.col.f32.f16.f16.f32 "
        "{%0,%1,%2,%3}, {%4,%5,%6,%7}, {%8,%9}, {%0,%1,%2,%3};"
        : "+f"(c[0]), "+f"(c[1]), "+f"(c[2]), "+f"(c[3])
        : "r"(a[0]), "r"(a[1]), "r"(a[2]), "r"(a[3]), "r"(b[0]), "r"(b[1]));
}

__device__ __forceinline__ void split2(float v, h16& h, h16& l) {
    h = __float2half_rn(v);
    l = __float2half_rn(v - __half2float(h));
}

// ---------------------------------------------------------------------------
// HMMA GEMM (NT): C[M,N] = sum_k (Ahi+Alo)[m,k]*(Bhi+Blo)[n,k]
// TERMS==3: AhBh + AhBl + AlBh.  TERMS==2: AhBh + AlBh (B-lo dropped).
// CTA 128x128, BK=64, 8 warps (2x4) of 64x32, 3-stage cp.async pipeline,
// single __syncthreads per k-iteration.
// Tile: 128 rows x 64 halves (128B row), chunk swizzle c ^ (row & 7).
// EPI==0: C = acc + bias[n], split-stored fp16 hi/lo. EPI==1: fp32 store.
// ---------------------------------------------------------------------------
#define TILE_B  16384           // 128 rows x 64 halves x 2B
#define STAGE_B 65536           // 4 tiles (Ah, Al, Bh, Bl)

template<int EPI, int TERMS>
__global__ __launch_bounds__(256) void mm_kernel(
    const h16* __restrict__ Ahi, const h16* __restrict__ Alo,
    const h16* __restrict__ Bhi, const h16* __restrict__ Blo,
    int K, long long sA, long long sB,
    const float* __restrict__ bias,
    float* __restrict__ Cf, long long sC, int ldc,
    h16* __restrict__ Chi, h16* __restrict__ Clo)
{
    extern __shared__ char dsm[];
    const int tid = threadIdx.x;
    const int wid = tid >> 5;
    const int lane = tid & 31;
    const int warp_m = wid >> 2;          // 0..1 (64 rows each)
    const int warp_n = wid & 3;           // 0..3 (32 cols each)
    const int z = blockIdx.z;
    const int bm0 = blockIdx.y * 128;
    const int bn0 = blockIdx.x * 128;

    const uint32_t sbase = (smem_u32(dsm) + 1023u) & ~1023u;

    const h16* pt[4] = {
        Ahi + (size_t)z * sA + (size_t)bm0 * K,
        Alo + (size_t)z * sA + (size_t)bm0 * K,
        Bhi + (size_t)z * sB + (size_t)bn0 * K,
        Blo + (size_t)z * sB + (size_t)bn0 * K };

    // fill one stage: tiles of 128 rows x 64 halves (128B), swizzle c^(row&7)
    auto fill = [&](int stage, int k0) {
        uint32_t sb = sbase + stage * STAGE_B;
        #pragma unroll
        for (int t = 0; t < 4; ++t) {
            if (TERMS == 2 && t == 3) continue;   // B-lo tile unused
            #pragma unroll
            for (int rpt = 0; rpt < 4; ++rpt) {
                int idx = rpt * 256 + tid;
                int row = idx >> 3, c = idx & 7;
                uint32_t phys = (uint32_t)(c ^ (row & 7));
                uint32_t dst = sb + t * TILE_B + row * 128 + phys * 16;
                cp16(dst, pt[t] + (size_t)row * K + k0 + c * 8);
            }
        }
        CP_COMMIT();
    };

    float acc[4][4][4];
    #pragma unroll
    for (int i = 0; i < 4; ++i)
        #pragma unroll
        for (int j = 0; j < 4; ++j)
            #pragma unroll
            for (int k = 0; k < 4; ++k) acc[i][j][k] = 0.f;

    const int NK = K >> 6;
    fill(0, 0);
    fill(1, 64);

    // B x4 ldsm lane mapping: grp 0..3 -> {nt_even k-lo, nt_even k-hi,
    //                                      nt_odd k-lo, nt_odd k-hi}
    const int grp = lane >> 3;
    const int bro = warp_n * 32 + ((grp >> 1) & 1) * 8 + (lane & 7);
    const int gch = grp & 1;
    const int arow = warp_m * 64 + (lane & 15);
    const int ach = lane >> 4;

    for (int i = 0; i < NK; ++i) {
        if (i + 1 < NK) asm volatile("cp.async.wait_group 1;" ::: "memory");
        else            asm volatile("cp.async.wait_group 0;" ::: "memory");
        __syncthreads();
        if (i + 2 < NK) fill((i + 2) % 3, (i + 2) * 64);

        const uint32_t sb  = sbase + (i % 3) * STAGE_B;
        const uint32_t bAh = sb;
        const uint32_t bAl = sb + TILE_B;
        const uint32_t bBh = sb + 2 * TILE_B;
        const uint32_t bBl = sb + 3 * TILE_B;

        #pragma unroll
        for (int kk = 0; kk < 4; ++kk) {
            uint32_t aH[4][4], aL[4][4], bH[8], bL[8];
            const int ac = kk * 2 + ach;
            const int bc = kk * 2 + gch;
            // A hi: 4 x4 loads (16 rows x 16 k each)
            #pragma unroll
            for (int mt = 0; mt < 4; ++mt) {
                int row = arow + mt * 16;
                uint32_t addr = bAh + row * 128 + (uint32_t)(ac ^ (row & 7)) * 16;
                ldsm_x4(aH[mt], addr);
            }
            // B hi: 2 x4 loads cover nt 0..3, both k halves
            #pragma unroll
            for (int p = 0; p < 2; ++p) {
                int row = bro + p * 16;
                uint32_t addr = bBh + row * 128 + (uint32_t)(bc ^ (row & 7)) * 16;
                ldsm_x4(&bH[p * 4], addr);
            }
            #pragma unroll
            for (int mt = 0; mt < 4; ++mt)
                #pragma unroll
                for (int nt = 0; nt < 4; ++nt) mma16816(acc[mt][nt], aH[mt], &bH[nt * 2]);

            if (TERMS == 3) {
                #pragma unroll
                for (int p = 0; p < 2; ++p) {
                    int row = bro + p * 16;
                    uint32_t addr = bBl + row * 128 + (uint32_t)(bc ^ (row & 7)) * 16;
                    ldsm_x4(&bL[p * 4], addr);
                }
                #pragma unroll
                for (int mt = 0; mt < 4; ++mt)
                    #pragma unroll
                    for (int nt = 0; nt < 4; ++nt) mma16816(acc[mt][nt], aH[mt], &bL[nt * 2]);
            }

            // A lo
            #pragma unroll
            for (int mt = 0; mt < 4; ++mt) {
                int row = arow + mt * 16;
                uint32_t addr = bAl + row * 128 + (uint32_t)(ac ^ (row & 7)) * 16;
                ldsm_x4(aL[mt], addr);
            }
            #pragma unroll
            for (int mt = 0; mt < 4; ++mt)
                #pragma unroll
                for (int nt = 0; nt < 4; ++nt) mma16816(acc[mt][nt], aL[mt], &bH[nt * 2]);
        }
        // no trailing barrier: top-of-loop barrier protects stage reuse
    }

    // epilogue
    #pragma unroll
    for (int mt = 0; mt < 4; ++mt) {
        #pragma unroll
        for (int nt = 0; nt < 4; ++nt) {
            const int m0 = bm0 + warp_m * 64 + mt * 16 + (lane >> 2);
            const int n0 = bn0 + warp_n * 32 + nt * 8 + 2 * (lane & 3);
            float* c = acc[mt][nt];
            if (EPI == 1) {
                float* r0 = Cf + (size_t)z * sC + (size_t)m0 * ldc + n0;
                float* r1 = Cf + (size_t)z * sC + (size_t)(m0 + 8) * ldc + n0;
                *(float2*)r0 = make_float2(c[0], c[1]);
                *(float2*)r1 = make_float2(c[2], c[3]);
            } else {
                float b0 = bias[n0], b1 = bias[n0 + 1];
                h16 h0, l0, h1, l1;
                split2(c[0] + b0, h0, l0); split2(c[1] + b1, h1, l1);
                *(__half2*)(Chi + (size_t)m0 * ldc + n0) = __halves2half2(h0, h1);
                *(__half2*)(Clo + (size_t)m0 * ldc + n0) = __halves2half2(l0, l1);
                split2(c[2] + b0, h0, l0); split2(c[3] + b1, h1, l1);
                *(__half2*)(Chi + (size_t)(m0 + 8) * ldc + n0) = __halves2half2(h0, h1);
                *(__half2*)(Clo + (size_t)(m0 + 8) * ldc + n0) = __halves2half2(l0, l1);
            }
        }
    }
}

// ---------------------------------------------------------------------------
// elementwise fp32 -> (hi, lo) fp16 split
// ---------------------------------------------------------------------------
__global__ __launch_bounds__(256) void split_kernel(
    const float4* __restrict__ in, __half2* __restrict__ hi,
    __half2* __restrict__ lo, int n4)
{
    int i = blockIdx.x * 256 + threadIdx.x;
    if (i >= n4) return;
    float4 v = in[i];
    h16 h0, l0, h1, l1, h2, l2, h3, l3;
    split2(v.x, h0, l0); split2(v.y, h1, l1);
    split2(v.z, h2, l2); split2(v.w, h3, l3);
    hi[2 * i + 0] = __halves2half2(h0, h1);
    hi[2 * i + 1] = __halves2half2(h2, h3);
    lo[2 * i + 0] = __halves2half2(l0, l1);
    lo[2 * i + 1] = __halves2half2(l2, l3);
}

// ---------------------------------------------------------------------------
// batched transpose + split: in [R, C] fp32 -> out [C, R] (hi, lo) fp16.
// If rh/rl nonnull also emits row-major split (single pass over input).
// ---------------------------------------------------------------------------
__global__ __launch_bounds__(256) void transpose_split_kernel(
    const float* __restrict__ in, h16* __restrict__ ohi, h16* __restrict__ olo,
    h16* __restrict__ rh, h16* __restrict__ rl, int R, int C)
{
    __shared__ float t[32][33];
    const size_t bofs = (size_t)blockIdx.z * R * C;
    const float* ip = in + bofs;
    const int c0 = blockIdx.x * 32, r0 = blockIdx.y * 32;
    const int x = threadIdx.x & 31;
    const int ty = threadIdx.x >> 5;   // 0..7
    #pragma unroll
    for (int dy = 0; dy < 32; dy += 8) {
        float v = ip[(size_t)(r0 + ty + dy) * C + c0 + x];
        t[ty + dy][x] = v;
        if (rh) {
            h16 h, l; split2(v, h, l);
            size_t ridx = bofs + (size_t)(r0 + ty + dy) * C + c0 + x;
            rh[ridx] = h;
            rl[ridx] = l;
        }
    }
    __syncthreads();
    #pragma unroll
    for (int dy = 0; dy < 32; dy += 8) {
        float v = t[x][ty + dy];
        h16 h, l; split2(v, h, l);
        size_t oidx = bofs + (size_t)(c0 + ty + dy) * R + r0 + x;
        ohi[oidx] = h;
        olo[oidx] = l;
    }
}

// ---------------------------------------------------------------------------
// row softmax over q (rows of G^T [B*LA, LQ]); writes split probs * 1/sum.
// ---------------------------------------------------------------------------
__global__ __launch_bounds__(256) void softmax_split_kernel(
    const float* __restrict__ G, h16* __restrict__ Phi, h16* __restrict__ Plo)
{
    __shared__ float red[256];
    const size_t row = blockIdx.x;
    const float4* g4 = (const float4*)(G + row * LQ);
    const int tid = threadIdx.x;

    float4 v[2];
    v[0] = g4[tid];
    v[1] = g4[tid + 256];

    float m = fmaxf(fmaxf(fmaxf(v[0].x, v[0].y), fmaxf(v[0].z, v[0].w)),
                    fmaxf(fmaxf(v[1].x, v[1].y), fmaxf(v[1].z, v[1].w)));
    red[tid] = m; __syncthreads();
    #pragma unroll
    for (int s = 128; s > 0; s >>= 1) {
        if (tid < s) red[tid] = fmaxf(red[tid], red[tid + s]);
        __syncthreads();
    }
    m = red[0]; __syncthreads();

    float ssum = 0.f;
    #pragma unroll
    for (int k = 0; k < 2; ++k) {
        v[k].x = __expf(v[k].x - m); ssum += v[k].x;
        v[k].y = __expf(v[k].y - m); ssum += v[k].y;
        v[k].z = __expf(v[k].z - m); ssum += v[k].z;
        v[k].w = __expf(v[k].w - m); ssum += v[k].w;
    }
    red[tid] = ssum; __syncthreads();
    #pragma unroll
    for (int s = 128; s > 0; s >>= 1) {
        if (tid < s) red[tid] += red[tid + s];
        __syncthreads();
    }
    const float inv = 1.0f / red[0];

    __half2* ph2 = (__half2*)(Phi + row * LQ);
    __half2* pl2 = (__half2*)(Plo + row * LQ);
    #pragma unroll
    for (int k = 0; k < 2; ++k) {
        int base = (tid + k * 256) * 2;
        h16 h0, l0, h1, l1;
        split2(v[k].x * inv, h0, l0); split2(v[k].y * inv, h1, l1);
        ph2[base] = __halves2half2(h0, h1);
        pl2[base] = __halves2half2(l0, l1);
        split2(v[k].z * inv, h0, l0); split2(v[k].w * inv, h1, l1);
        ph2[base + 1] = __halves2half2(h0, h1);
        pl2[base + 1] = __halves2half2(l0, l1);
    }
}

// ---------------------------------------------------------------------------
extern "C" void kernel_launch(void* const* d_in, const int* in_sizes, int n_in,
                              void* d_out, int out_size)
{
    const float* q    = (const float*)d_in[0];   // [B, LQ, HD]
    const float* a    = (const float*)d_in[1];   // [B, LA, HD]
    const float* w    = (const float*)d_in[2];   // [HD, HD]
    const float* bias = (const float*)d_in[3];   // [HD]
    float* out = (float*)d_out;                  // [B, LA, HD]
    (void)in_sizes; (void)n_in; (void)out_size;

    h16 *wTh, *wTl, *qh, *ql, *qTh, *qTl, *ah, *al, *g1h, *g1l, *ph, *pl;
    float* G;
    cudaGetSymbolAddress((void**)&wTh, g_wT_hi);
    cudaGetSymbolAddress((void**)&wTl, g_wT_lo);
    cudaGetSymbolAddress((void**)&qh,  g_q_hi);
    cudaGetSymbolAddress((void**)&ql,  g_q_lo);
    cudaGetSymbolAddress((void**)&qTh, g_qT_hi);
    cudaGetSymbolAddress((void**)&qTl, g_qT_lo);
    cudaGetSymbolAddress((void**)&ah,  g_a_hi);
    cudaGetSymbolAddress((void**)&al,  g_a_lo);
    cudaGetSymbolAddress((void**)&g1h, g_G1_hi);
    cudaGetSymbolAddress((void**)&g1l, g_G1_lo);
    cudaGetSymbolAddress((void**)&G,   g_G);
    cudaGetSymbolAddress((void**)&ph,  g_P_hi);
    cudaGetSymbolAddress((void**)&pl,  g_P_lo);

    const int dyn_smem = 3 * STAGE_B + 1024;
    cudaFuncSetAttribute(mm_kernel<0,3>, cudaFuncAttributeMaxDynamicSharedMemorySize, dyn_smem);
    cudaFuncSetAttribute(mm_kernel<1,3>, cudaFuncAttributeMaxDynamicSharedMemorySize, dyn_smem);
    cudaFuncSetAttribute(mm_kernel<1,2>, cudaFuncAttributeMaxDynamicSharedMemorySize, dyn_smem);

    // 1) input conversions
    {
        int n4 = (B_ * LQ * HD) / 4;
        split_kernel<<<n4 / 256, 256>>>((const float4*)a, (__half2*)ah, (__half2*)al, n4);
    }
    {
        dim3 grid(HD / 32, HD / 32, 1);
        transpose_split_kernel<<<grid, 256>>>(w, wTh, wTl, nullptr, nullptr, HD, HD);
    }
    {
        // fused: q -> qh/ql (row-major) + qTh/qTl (transposed), one pass
        dim3 grid(HD / 32, LQ / 32, B_);
        transpose_split_kernel<<<grid, 256>>>(q, qTh, qTl, qh, ql, LQ, HD);
    }

    // 2) G1 = q @ w + b  (M=B*LQ, N=HD, K=HD), split-stored fp16
    {
        dim3 grid(HD / 128, (B_ * LQ) / 128, 1);
        mm_kernel<0,3><<<grid, 256, dyn_smem>>>(qh, ql, wTh, wTl, HD, 0, 0,
                                                bias, nullptr, 0, HD, g1h, g1l);
    }
    // 3) G^T[a,q] = a @ G1^T  (per batch M=LA, N=LQ, K=HD), fp32
    {
        dim3 grid(LQ / 128, LA / 128, B_);
        mm_kernel<1,3><<<grid, 256, dyn_smem>>>(ah, al, g1h, g1l, HD,
                                                (long long)LA * HD, (long long)LQ * HD,
                                                nullptr, G, (long long)LA * LQ, LQ,
                                                nullptr, nullptr);
    }
    // 4) row softmax over q + split probs
    softmax_split_kernel<<<B_ * LA, 256>>>(G, ph, pl);

    // 5) out[a,h] = P[a,q] @ qT[h,q]^T  (per batch M=LA, N=HD, K=LQ),
    //    2-term (q_lo dropped), fp32
    {
        dim3 grid(HD / 128, LA / 128, B_);
        mm_kernel<1,2><<<grid, 256, dyn_smem>>>(ph, pl, qTh, qTl, LQ,
                                                (long long)LA * LQ, (long long)HD * LQ,
                                                nullptr, out, (long long)LA * HD, HD,
                                                nullptr, nullptr);
    }
}